// round 16
// baseline (speedup 1.0000x reference)
#include <cuda_runtime.h>
#include <cuda_fp16.h>
#include <cstdint>

// Problem constants
#define NROWS 8192          // n = 2*B
#define BROWS 4096          // B
#define DDIM  256           // feature dim
#define BLK   128           // tile edge
#define NT    64            // NROWS/BLK
#define NTRI  (NT*(NT+1)/2) // 2080 upper-triangular tiles
#define KC    64            // k columns per chunk (128B of fp16)
#define NCH   (DDIM/KC)     // 4 chunks per tile
#define ROWB  144           // smem row stride bytes (128B data + 16B pad)
#define MATB  (BLK*ROWB)    // 18432 B per matrix buffer
#define STAGEB (2*MATB)     // 36864 B per stage (A, B)
#define NSTAGE 3
#define DYN_SMEM (NSTAGE*STAGEB) // 110592 B
#define PREPB 256           // prep blocks

// Device scratch (no allocations allowed)
__device__ float  g_sq[NROWS];
__device__ float  g_colpart[PREPB][DDIM];
__device__ double g_s1part[PREPB];
__device__ double g_result;
__device__ float  g_scale;     // 1/(16*bandwidth)
__device__ __half g_h[NROWS * DDIM];
__device__ unsigned int g_prep_count = 0;
__device__ unsigned int g_pair_count = 0;

// ---------------------------------------------------------------------------
__device__ __forceinline__ uint32_t smem_u32(const void* p) {
    uint32_t a;
    asm("{ .reg .u64 t; cvta.to.shared.u64 t, %1; cvt.u32.u64 %0, t; }"
        : "=r"(a) : "l"(p));
    return a;
}

__device__ __forceinline__ void ldsm4(uint32_t* r, uint32_t addr) {
    asm volatile("ldmatrix.sync.aligned.m8n8.x4.shared.b16 {%0,%1,%2,%3}, [%4];"
                 : "=r"(r[0]), "=r"(r[1]), "=r"(r[2]), "=r"(r[3]) : "r"(addr));
}

__device__ __forceinline__ void mma16816(float* c, const uint32_t* a,
                                         uint32_t b0, uint32_t b1) {
    asm volatile(
        "mma.sync.aligned.m16n8k16.row.col.f32.f16.f16.f32 "
        "{%0,%1,%2,%3}, {%4,%5,%6,%7}, {%8,%9}, {%0,%1,%2,%3};"
        : "+f"(c[0]), "+f"(c[1]), "+f"(c[2]), "+f"(c[3])
        : "r"(a[0]), "r"(a[1]), "r"(a[2]), "r"(a[3]), "r"(b0), "r"(b1));
}

__device__ __forceinline__ float ex2f(float x) {
    float r;
    asm("ex2.approx.ftz.f32 %0, %1;" : "=f"(r) : "f"(x));
    return r;
}

#define CP_ASYNC16(dst, src) \
    asm volatile("cp.async.cg.shared.global [%0], [%1], 16;" \
                 :: "r"(dst), "l"(src) : "memory")
#define CP_COMMIT() asm volatile("cp.async.commit_group;" ::: "memory")
#define CP_WAIT1()  asm volatile("cp.async.wait_group 1;" ::: "memory")

// ---------------------------------------------------------------------------
// Fused prep: row norms, per-block column partials + s1 partials, fp16 cast.
// LAST block reduces partials -> bandwidth -> g_scale, zeroes g_result.
__global__ void prep_kernel(const float* __restrict__ src,
                            const float* __restrict__ tgt) {
    __shared__ float  csum_s[8][DDIM];
    __shared__ double s1_s[8];
    __shared__ double red_d[256];
    __shared__ bool   is_last;

    int tid  = threadIdx.x;
    int lane = tid & 31;
    int w    = tid >> 5;
    int b    = blockIdx.x;

    float csum[8] = {0, 0, 0, 0, 0, 0, 0, 0};
    double s1 = 0.0;

    #pragma unroll
    for (int i = 0; i < 4; i++) {
        int r = b * 32 + w * 4 + i;
        const float2* row = (const float2*)((r < BROWS)
                            ? (src + (size_t)r * DDIM)
                            : (tgt + (size_t)(r - BROWS) * DDIM));
        float sq = 0.0f;
        #pragma unroll
        for (int k = 0; k < 4; k++) {
            int idx = lane + 32 * k;            // float2 index 0..127
            float2 x = row[idx];
            sq = fmaf(x.x, x.x, sq);
            sq = fmaf(x.y, x.y, sq);
            csum[2 * k]     += x.x;
            csum[2 * k + 1] += x.y;
            ((half2*)(g_h + (size_t)r * DDIM))[idx] = __floats2half2_rn(x.x, x.y);
        }
        #pragma unroll
        for (int s = 16; s > 0; s >>= 1) sq += __shfl_xor_sync(0xFFFFFFFFu, sq, s);
        if (lane == 0) { g_sq[r] = sq; s1 += (double)sq; }
    }

    #pragma unroll
    for (int k = 0; k < 4; k++) {
        csum_s[w][64 * k + 2 * lane]     = csum[2 * k];
        csum_s[w][64 * k + 2 * lane + 1] = csum[2 * k + 1];
    }
    if (lane == 0) s1_s[w] = s1;
    __syncthreads();

    float t = 0.0f;
    #pragma unroll
    for (int w2 = 0; w2 < 8; w2++) t += csum_s[w2][tid];
    g_colpart[b][tid] = t;
    if (tid == 0) {
        double bs1 = 0.0;
        #pragma unroll
        for (int w2 = 0; w2 < 8; w2++) bs1 += s1_s[w2];
        g_s1part[b] = bs1;
    }

    __threadfence();
    __syncthreads();
    if (tid == 0) {
        unsigned int old = atomicInc(&g_prep_count, PREPB - 1);
        is_last = (old == PREPB - 1);
    }
    __syncthreads();
    if (!is_last) return;
    __threadfence();

    float cs = 0.0f;
    #pragma unroll 4
    for (int b2 = 0; b2 < PREPB; b2++) cs += g_colpart[b2][tid];
    double ssq = (double)cs * (double)cs;
    double s1v = g_s1part[tid];

    red_d[tid] = ssq;
    __syncthreads();
    #pragma unroll
    for (int s = 128; s > 0; s >>= 1) {
        if (tid < s) red_d[tid] += red_d[tid + s];
        __syncthreads();
    }
    double ss = red_d[0];
    __syncthreads();
    red_d[tid] = s1v;
    __syncthreads();
    #pragma unroll
    for (int s = 128; s > 0; s >>= 1) {
        if (tid < s) red_d[tid] += red_d[tid + s];
        __syncthreads();
    }
    if (tid == 0) {
        double S1 = red_d[0];
        const double n = (double)NROWS;
        double sum_l2 = 2.0 * n * S1 - 2.0 * ss;
        double bw = sum_l2 / (n * n - n) / 4.0;   // / KERNEL_MUL^(KERNEL_NUM/2)
        g_scale = (float)(1.0 / (bw * 16.0));     // largest sigma = bw*2^4
        g_result = 0.0;
    }
}

// ---------------------------------------------------------------------------
// Issue 8 cp.async (16B) per thread: one KC=64 chunk of A and B fp16 tiles.
__device__ __forceinline__ void prefetch_chunk(
    uint32_t sbase, const __half* A, const __half* B, int k0, int tid) {
    #pragma unroll
    for (int l = 0; l < 4; l++) {
        int f   = tid + l * 256;      // 0..1023
        int r   = f >> 3;             // row 0..127
        int c16 = f & 7;              // 16B group within 128B row
        uint32_t so = (uint32_t)r * ROWB + (uint32_t)c16 * 16;
        size_t  go = (size_t)r * DDIM + k0 + c16 * 8;
        CP_ASYNC16(sbase + so,        (const void*)(A + go));
        CP_ASYNC16(sbase + MATB + so, (const void*)(B + go));
    }
}

// ---------------------------------------------------------------------------
// HMMA pair kernel (r13 core, stagger removed): one 128x128 tile per CTA,
// f32-acc fp16 mma.sync, 3-stage cp.async ring, software-pipelined k-loop,
// clamp-free fp32 log2-domain epilogue, fused finalize.
__global__ void __launch_bounds__(256, 2)
pair16_kernel(float* __restrict__ out) {
    extern __shared__ __align__(16) char dyn[];
    __shared__ float sqa[BLK];
    __shared__ float sqb[BLK];

    int tid  = threadIdx.x;
    int lane = tid & 31;
    int wid  = tid >> 5;
    int wy   = wid >> 2;      // 0..1
    int wx   = wid & 3;       // 0..3

    // Closed-form triangular decode: bi = row of tile, bj >= bi
    int rem = blockIdx.x;
    int bi = (int)((2.0f * NT + 1.0f
              - sqrtf((float)((2 * NT + 1) * (2 * NT + 1) - 8 * rem))) * 0.5f);
    while (bi * NT - bi * (bi - 1) / 2 > rem) bi--;
    while ((bi + 1) * NT - (bi + 1) * bi / 2 <= rem) bi++;
    int bj = bi + rem - (bi * NT - bi * (bi - 1) / 2);

    const __half* A = g_h + (size_t)bi * BLK * DDIM;
    const __half* B = g_h + (size_t)bj * BLK * DDIM;

    uint32_t dynb = smem_u32(dyn);

    // Prologue: 2 chunks in flight
    prefetch_chunk(dynb + 0 * STAGEB, A, B, 0, tid);
    CP_COMMIT();
    prefetch_chunk(dynb + 1 * STAGEB, A, B, KC, tid);
    CP_COMMIT();

    if (tid < BLK) {
        sqa[tid] = g_sq[bi * BLK + tid];
        sqb[tid] = g_sq[bj * BLK + tid];
    }

    float acc[4][4][4];
    #pragma unroll
    for (int mt = 0; mt < 4; mt++)
        #pragma unroll
        for (int nt = 0; nt < 4; nt++)
            #pragma unroll
            for (int e = 0; e < 4; e++) acc[mt][nt][e] = 0.0f;

    // Per-lane ldmatrix offsets (bytes) within a matrix buffer
    uint32_t a_off = (uint32_t)(wy * 64 + (lane & 15)) * ROWB + ((lane >> 4) << 4);
    uint32_t b_off = (uint32_t)(wx * 32 + (lane & 7) + ((lane >> 4) << 3)) * ROWB
                   + (((lane >> 3) & 1) << 4);

    int stage = 0;
    #pragma unroll
    for (int c = 0; c < NCH; c++) {
        CP_WAIT1();              // chunk c complete (<=1 younger group pending)
        __syncthreads();         // chunk c visible to all; stage c+2 free
        if (c + 2 < NCH) {
            int ps = stage + 2; if (ps >= NSTAGE) ps -= NSTAGE;
            prefetch_chunk(dynb + ps * STAGEB, A, B, (c + 2) * KC, tid);
        }
        CP_COMMIT();             // one group per chunk (possibly empty)

        uint32_t uA = dynb + stage * STAGEB + a_off;
        uint32_t uB = dynb + stage * STAGEB + MATB + b_off;
        if (++stage == NSTAGE) stage = 0;

        // Software-pipelined k-loop: A fragments double-buffered (prefetched
        // before the MMAs), B reloaded after the MMAs (WAR-safe; latency
        // hidden under the tensor drain).
        uint32_t aF[2][4][4];
        uint32_t bC[2][4];
        #pragma unroll
        for (int bp = 0; bp < 2; bp++)
            ldsm4(bC[bp], uB + (uint32_t)bp * 16 * ROWB);
        #pragma unroll
        for (int mt = 0; mt < 4; mt++)
            ldsm4(aF[0][mt], uA + (uint32_t)mt * 16 * ROWB);

        #pragma unroll
        for (int ks = 0; ks < 4; ks++) {
            const int cb = ks & 1;
            const int nb = cb ^ 1;
            if (ks < 3) {
                uint32_t kb = (uint32_t)(ks + 1) * 32;
                #pragma unroll
                for (int mt = 0; mt < 4; mt++)
                    ldsm4(aF[nb][mt], uA + (uint32_t)mt * 16 * ROWB + kb);
            }
            #pragma unroll
            for (int mt = 0; mt < 4; mt++)
                #pragma unroll
                for (int nt = 0; nt < 4; nt++)
                    mma16816(acc[mt][nt], aF[cb][mt],
                             bC[nt >> 1][(nt & 1) * 2],
                             bC[nt >> 1][(nt & 1) * 2 + 1]);
            if (ks < 3) {
                uint32_t kb = (uint32_t)(ks + 1) * 32;
                #pragma unroll
                for (int bp = 0; bp < 2; bp++)
                    ldsm4(bC[bp], uB + (uint32_t)bp * 16 * ROWB + kb);
            }
        }
    }

    // Epilogue in log2-domain: K = exp2(f2*d - hi - hj), 4 squarings give the
    // 5-kernel sum. FMA-chained: last squaring folded into the psum update.
    const float LG2E = 1.4426950408889634f;
    float clg = g_scale * LG2E;
    float f2  = 2.0f * clg;
    int r0 = wy * 64 + (lane >> 2);
    int c0 = wx * 32 + 2 * (lane & 3);

    float hi[8], hj[8];
    #pragma unroll
    for (int mt = 0; mt < 4; mt++) {
        hi[mt * 2]     = clg * sqa[r0 + mt * 16];
        hi[mt * 2 + 1] = clg * sqa[r0 + mt * 16 + 8];
    }
    #pragma unroll
    for (int nt = 0; nt < 4; nt++) {
        hj[nt * 2]     = clg * sqb[c0 + nt * 8];
        hj[nt * 2 + 1] = clg * sqb[c0 + nt * 8 + 1];
    }

    float psum[4] = {0.0f, 0.0f, 0.0f, 0.0f};
    #pragma unroll
    for (int mt = 0; mt < 4; mt++) {
        #pragma unroll
        for (int nt = 0; nt < 4; nt++) {
            #pragma unroll
            for (int e = 0; e < 4; e++) {
                float d   = acc[mt][nt][e];
                float arg = fmaf(f2, d,
                                 -(hi[mt * 2 + (e >> 1)] + hj[nt * 2 + (e & 1)]));
                float e1  = ex2f(arg);
                float e2  = e1 * e1;
                float s1  = fmaf(e1, e1, e1);    // e1 + e2
                float e4  = e2 * e2;
                float s2  = fmaf(e2, e2, s1);    // + e4
                float e8  = e4 * e4;
                float s3  = fmaf(e4, e4, s2);    // + e8
                psum[mt] += fmaf(e8, e8, s3);    // + e16
            }
        }
    }
    double local = (double)((psum[0] + psum[1]) + (psum[2] + psum[3]));

    // Tile weight: sign from halves, x2 for off-diagonal (mirror tile)
    double w = ((bi < NT / 2) == (bj < NT / 2)) ? 1.0 : -1.0;
    if (bj > bi) w *= 2.0;
    local *= w;

    // Warp shfl reduce (double) + one atomic per warp
    #pragma unroll
    for (int s = 16; s > 0; s >>= 1)
        local += __shfl_xor_sync(0xFFFFFFFFu, local, s);
    if (lane == 0) {
        atomicAdd(&g_result, local);
        __threadfence();
    }

    // Fused finalize: last CTA writes the output
    __syncthreads();
    if (tid == 0) {
        unsigned int old = atomicInc(&g_pair_count, NTRI - 1);
        if (old == NTRI - 1) {
            __threadfence();
            double r = *((volatile double*)&g_result);
            out[0] = (float)(r * (1.0 / ((double)BROWS * (double)BROWS)));
        }
    }
}

// ---------------------------------------------------------------------------
extern "C" void kernel_launch(void* const* d_in, const int* in_sizes, int n_in,
                              void* d_out, int out_size) {
    const float* src = (const float*)d_in[0];
    const float* tgt = (const float*)d_in[1];
    float* out = (float*)d_out;
    (void)in_sizes; (void)n_in; (void)out_size;

    cudaFuncSetAttribute(pair16_kernel,
                         cudaFuncAttributeMaxDynamicSharedMemorySize, DYN_SMEM);

    prep_kernel<<<PREPB, 256>>>(src, tgt);
    pair16_kernel<<<NTRI, 256, DYN_SMEM>>>(out);
}

// round 17
// speedup vs baseline: 1.1343x; 1.1343x over previous
#include <cuda_runtime.h>
#include <cuda_fp16.h>
#include <cstdint>

// Problem constants
#define NROWS 8192          // n = 2*B
#define BROWS 4096          // B
#define DDIM  256           // feature dim
#define BLK   128           // tile edge
#define NT    64            // NROWS/BLK
#define NTRI  (NT*(NT+1)/2) // 2080 upper-triangular tiles
#define KC    64            // k columns per chunk (128B of fp16)
#define NCH   (DDIM/KC)     // 4 chunks per tile
#define ROWB  144           // smem row stride bytes (128B data + 16B pad)
#define MATB  (BLK*ROWB)    // 18432 B per matrix buffer
#define STAGEB (2*MATB)     // 36864 B per stage (A, B)
#define NSTAGE 3
#define DYN_SMEM (NSTAGE*STAGEB) // 110592 B
#define PREPB 256           // prep blocks

// Device scratch (no allocations allowed)
__device__ float  g_sq[NROWS];
__device__ float  g_colpart[PREPB][DDIM];
__device__ double g_s1part[PREPB];
__device__ double g_result;
__device__ float  g_scale;     // 1/(16*bandwidth)
__device__ __half g_h[NROWS * DDIM];
__device__ unsigned int g_prep_count = 0;
__device__ unsigned int g_pair_count = 0;

// ---------------------------------------------------------------------------
__device__ __forceinline__ uint32_t smem_u32(const void* p) {
    uint32_t a;
    asm("{ .reg .u64 t; cvta.to.shared.u64 t, %1; cvt.u32.u64 %0, t; }"
        : "=r"(a) : "l"(p));
    return a;
}

__device__ __forceinline__ void ldsm4(uint32_t* r, uint32_t addr) {
    asm volatile("ldmatrix.sync.aligned.m8n8.x4.shared.b16 {%0,%1,%2,%3}, [%4];"
                 : "=r"(r[0]), "=r"(r[1]), "=r"(r[2]), "=r"(r[3]) : "r"(addr));
}

__device__ __forceinline__ void mma16816(float* c, const uint32_t* a,
                                         uint32_t b0, uint32_t b1) {
    asm volatile(
        "mma.sync.aligned.m16n8k16.row.col.f32.f16.f16.f32 "
        "{%0,%1,%2,%3}, {%4,%5,%6,%7}, {%8,%9}, {%0,%1,%2,%3};"
        : "+f"(c[0]), "+f"(c[1]), "+f"(c[2]), "+f"(c[3])
        : "r"(a[0]), "r"(a[1]), "r"(a[2]), "r"(a[3]), "r"(b0), "r"(b1));
}

__device__ __forceinline__ float ex2f(float x) {
    float r;
    asm("ex2.approx.ftz.f32 %0, %1;" : "=f"(r) : "f"(x));
    return r;
}

#define CP_ASYNC16(dst, src) \
    asm volatile("cp.async.cg.shared.global [%0], [%1], 16;" \
                 :: "r"(dst), "l"(src) : "memory")
#define CP_COMMIT() asm volatile("cp.async.commit_group;" ::: "memory")
#define CP_WAIT1()  asm volatile("cp.async.wait_group 1;" ::: "memory")

// ---------------------------------------------------------------------------
// Fused prep: row norms, per-block column partials + s1 partials, fp16 cast.
// LAST block reduces partials -> bandwidth -> g_scale, zeroes g_result.
// (Exact r13/r15 version — no unroll pragma on the partial-reduce loop.)
__global__ void prep_kernel(const float* __restrict__ src,
                            const float* __restrict__ tgt) {
    __shared__ float  csum_s[8][DDIM];
    __shared__ double s1_s[8];
    __shared__ double red_d[256];
    __shared__ bool   is_last;

    int tid  = threadIdx.x;
    int lane = tid & 31;
    int w    = tid >> 5;
    int b    = blockIdx.x;

    float csum[8] = {0, 0, 0, 0, 0, 0, 0, 0};
    double s1 = 0.0;

    #pragma unroll
    for (int i = 0; i < 4; i++) {
        int r = b * 32 + w * 4 + i;
        const float2* row = (const float2*)((r < BROWS)
                            ? (src + (size_t)r * DDIM)
                            : (tgt + (size_t)(r - BROWS) * DDIM));
        float sq = 0.0f;
        #pragma unroll
        for (int k = 0; k < 4; k++) {
            int idx = lane + 32 * k;            // float2 index 0..127
            float2 x = row[idx];
            sq = fmaf(x.x, x.x, sq);
            sq = fmaf(x.y, x.y, sq);
            csum[2 * k]     += x.x;
            csum[2 * k + 1] += x.y;
            ((half2*)(g_h + (size_t)r * DDIM))[idx] = __floats2half2_rn(x.x, x.y);
        }
        #pragma unroll
        for (int s = 16; s > 0; s >>= 1) sq += __shfl_xor_sync(0xFFFFFFFFu, sq, s);
        if (lane == 0) { g_sq[r] = sq; s1 += (double)sq; }
    }

    #pragma unroll
    for (int k = 0; k < 4; k++) {
        csum_s[w][64 * k + 2 * lane]     = csum[2 * k];
        csum_s[w][64 * k + 2 * lane + 1] = csum[2 * k + 1];
    }
    if (lane == 0) s1_s[w] = s1;
    __syncthreads();

    float t = 0.0f;
    #pragma unroll
    for (int w2 = 0; w2 < 8; w2++) t += csum_s[w2][tid];
    g_colpart[b][tid] = t;
    if (tid == 0) {
        double bs1 = 0.0;
        #pragma unroll
        for (int w2 = 0; w2 < 8; w2++) bs1 += s1_s[w2];
        g_s1part[b] = bs1;
    }

    __threadfence();
    __syncthreads();
    if (tid == 0) {
        unsigned int old = atomicInc(&g_prep_count, PREPB - 1);
        is_last = (old == PREPB - 1);
    }
    __syncthreads();
    if (!is_last) return;
    __threadfence();

    float cs = 0.0f;
    for (int b2 = 0; b2 < PREPB; b2++) cs += g_colpart[b2][tid];
    double ssq = (double)cs * (double)cs;
    double s1v = g_s1part[tid];

    red_d[tid] = ssq;
    __syncthreads();
    #pragma unroll
    for (int s = 128; s > 0; s >>= 1) {
        if (tid < s) red_d[tid] += red_d[tid + s];
        __syncthreads();
    }
    double ss = red_d[0];
    __syncthreads();
    red_d[tid] = s1v;
    __syncthreads();
    #pragma unroll
    for (int s = 128; s > 0; s >>= 1) {
        if (tid < s) red_d[tid] += red_d[tid + s];
        __syncthreads();
    }
    if (tid == 0) {
        double S1 = red_d[0];
        const double n = (double)NROWS;
        double sum_l2 = 2.0 * n * S1 - 2.0 * ss;
        double bw = sum_l2 / (n * n - n) / 4.0;   // / KERNEL_MUL^(KERNEL_NUM/2)
        g_scale = (float)(1.0 / (bw * 16.0));     // largest sigma = bw*2^4
        g_result = 0.0;
    }
}

// ---------------------------------------------------------------------------
// Issue 8 cp.async (16B) per thread: one KC=64 chunk of A and B fp16 tiles.
__device__ __forceinline__ void prefetch_chunk(
    uint32_t sbase, const __half* A, const __half* B, int k0, int tid) {
    #pragma unroll
    for (int l = 0; l < 4; l++) {
        int f   = tid + l * 256;      // 0..1023
        int r   = f >> 3;             // row 0..127
        int c16 = f & 7;              // 16B group within 128B row
        uint32_t so = (uint32_t)r * ROWB + (uint32_t)c16 * 16;
        size_t  go = (size_t)r * DDIM + k0 + c16 * 8;
        CP_ASYNC16(sbase + so,        (const void*)(A + go));
        CP_ASYNC16(sbase + MATB + so, (const void*)(B + go));
    }
}

// ---------------------------------------------------------------------------
// HMMA pair kernel (r16, byte-identical): one 128x128 tile per CTA,
// f32-acc fp16 mma.sync, 3-stage cp.async ring, software-pipelined k-loop,
// clamp-free fp32 log2-domain epilogue (FMA-chained), fused finalize.
__global__ void __launch_bounds__(256, 2)
pair17_kernel(float* __restrict__ out) {
    extern __shared__ __align__(16) char dyn[];
    __shared__ float sqa[BLK];
    __shared__ float sqb[BLK];

    int tid  = threadIdx.x;
    int lane = tid & 31;
    int wid  = tid >> 5;
    int wy   = wid >> 2;      // 0..1
    int wx   = wid & 3;       // 0..3

    // Closed-form triangular decode: bi = row of tile, bj >= bi
    int rem = blockIdx.x;
    int bi = (int)((2.0f * NT + 1.0f
              - sqrtf((float)((2 * NT + 1) * (2 * NT + 1) - 8 * rem))) * 0.5f);
    while (bi * NT - bi * (bi - 1) / 2 > rem) bi--;
    while ((bi + 1) * NT - (bi + 1) * bi / 2 <= rem) bi++;
    int bj = bi + rem - (bi * NT - bi * (bi - 1) / 2);

    const __half* A = g_h + (size_t)bi * BLK * DDIM;
    const __half* B = g_h + (size_t)bj * BLK * DDIM;

    uint32_t dynb = smem_u32(dyn);

    // Prologue: 2 chunks in flight
    prefetch_chunk(dynb + 0 * STAGEB, A, B, 0, tid);
    CP_COMMIT();
    prefetch_chunk(dynb + 1 * STAGEB, A, B, KC, tid);
    CP_COMMIT();

    if (tid < BLK) {
        sqa[tid] = g_sq[bi * BLK + tid];
        sqb[tid] = g_sq[bj * BLK + tid];
    }

    float acc[4][4][4];
    #pragma unroll
    for (int mt = 0; mt < 4; mt++)
        #pragma unroll
        for (int nt = 0; nt < 4; nt++)
            #pragma unroll
            for (int e = 0; e < 4; e++) acc[mt][nt][e] = 0.0f;

    // Per-lane ldmatrix offsets (bytes) within a matrix buffer
    uint32_t a_off = (uint32_t)(wy * 64 + (lane & 15)) * ROWB + ((lane >> 4) << 4);
    uint32_t b_off = (uint32_t)(wx * 32 + (lane & 7) + ((lane >> 4) << 3)) * ROWB
                   + (((lane >> 3) & 1) << 4);

    int stage = 0;
    #pragma unroll
    for (int c = 0; c < NCH; c++) {
        CP_WAIT1();              // chunk c complete (<=1 younger group pending)
        __syncthreads();         // chunk c visible to all; stage c+2 free
        if (c + 2 < NCH) {
            int ps = stage + 2; if (ps >= NSTAGE) ps -= NSTAGE;
            prefetch_chunk(dynb + ps * STAGEB, A, B, (c + 2) * KC, tid);
        }
        CP_COMMIT();             // one group per chunk (possibly empty)

        uint32_t uA = dynb + stage * STAGEB + a_off;
        uint32_t uB = dynb + stage * STAGEB + MATB + b_off;
        if (++stage == NSTAGE) stage = 0;

        // Software-pipelined k-loop: A fragments double-buffered (prefetched
        // before the MMAs), B reloaded after the MMAs (WAR-safe; latency
        // hidden under the tensor drain).
        uint32_t aF[2][4][4];
        uint32_t bC[2][4];
        #pragma unroll
        for (int bp = 0; bp < 2; bp++)
            ldsm4(bC[bp], uB + (uint32_t)bp * 16 * ROWB);
        #pragma unroll
        for (int mt = 0; mt < 4; mt++)
            ldsm4(aF[0][mt], uA + (uint32_t)mt * 16 * ROWB);

        #pragma unroll
        for (int ks = 0; ks < 4; ks++) {
            const int cb = ks & 1;
            const int nb = cb ^ 1;
            if (ks < 3) {
                uint32_t kb = (uint32_t)(ks + 1) * 32;
                #pragma unroll
                for (int mt = 0; mt < 4; mt++)
                    ldsm4(aF[nb][mt], uA + (uint32_t)mt * 16 * ROWB + kb);
            }
            #pragma unroll
            for (int mt = 0; mt < 4; mt++)
                #pragma unroll
                for (int nt = 0; nt < 4; nt++)
                    mma16816(acc[mt][nt], aF[cb][mt],
                             bC[nt >> 1][(nt & 1) * 2],
                             bC[nt >> 1][(nt & 1) * 2 + 1]);
            if (ks < 3) {
                uint32_t kb = (uint32_t)(ks + 1) * 32;
                #pragma unroll
                for (int bp = 0; bp < 2; bp++)
                    ldsm4(bC[bp], uB + (uint32_t)bp * 16 * ROWB + kb);
            }
        }
    }

    // Epilogue in log2-domain: K = exp2(f2*d - hi - hj), 4 squarings give the
    // 5-kernel sum. FMA-chained: last squaring folded into the psum update.
    const float LG2E = 1.4426950408889634f;
    float clg = g_scale * LG2E;
    float f2  = 2.0f * clg;
    int r0 = wy * 64 + (lane >> 2);
    int c0 = wx * 32 + 2 * (lane & 3);

    float hi[8], hj[8];
    #pragma unroll
    for (int mt = 0; mt < 4; mt++) {
        hi[mt * 2]     = clg * sqa[r0 + mt * 16];
        hi[mt * 2 + 1] = clg * sqa[r0 + mt * 16 + 8];
    }
    #pragma unroll
    for (int nt = 0; nt < 4; nt++) {
        hj[nt * 2]     = clg * sqb[c0 + nt * 8];
        hj[nt * 2 + 1] = clg * sqb[c0 + nt * 8 + 1];
    }

    float psum[4] = {0.0f, 0.0f, 0.0f, 0.0f};
    #pragma unroll
    for (int mt = 0; mt < 4; mt++) {
        #pragma unroll
        for (int nt = 0; nt < 4; nt++) {
            #pragma unroll
            for (int e = 0; e < 4; e++) {
                float d   = acc[mt][nt][e];
                float arg = fmaf(f2, d,
                                 -(hi[mt * 2 + (e >> 1)] + hj[nt * 2 + (e & 1)]));
                float e1  = ex2f(arg);
                float e2  = e1 * e1;
                float s1  = fmaf(e1, e1, e1);    // e1 + e2
                float e4  = e2 * e2;
                float s2  = fmaf(e2, e2, s1);    // + e4
                float e8  = e4 * e4;
                float s3  = fmaf(e4, e4, s2);    // + e8
                psum[mt] += fmaf(e8, e8, s3);    // + e16
            }
        }
    }
    double local = (double)((psum[0] + psum[1]) + (psum[2] + psum[3]));

    // Tile weight: sign from halves, x2 for off-diagonal (mirror tile)
    double w = ((bi < NT / 2) == (bj < NT / 2)) ? 1.0 : -1.0;
    if (bj > bi) w *= 2.0;
    local *= w;

    // Warp shfl reduce (double) + one atomic per warp
    #pragma unroll
    for (int s = 16; s > 0; s >>= 1)
        local += __shfl_xor_sync(0xFFFFFFFFu, local, s);
    if (lane == 0) {
        atomicAdd(&g_result, local);
        __threadfence();
    }

    // Fused finalize: last CTA writes the output
    __syncthreads();
    if (tid == 0) {
        unsigned int old = atomicInc(&g_pair_count, NTRI - 1);
        if (old == NTRI - 1) {
            __threadfence();
            double r = *((volatile double*)&g_result);
            out[0] = (float)(r * (1.0 / ((double)BROWS * (double)BROWS)));
        }
    }
}

// ---------------------------------------------------------------------------
extern "C" void kernel_launch(void* const* d_in, const int* in_sizes, int n_in,
                              void* d_out, int out_size) {
    const float* src = (const float*)d_in[0];
    const float* tgt = (const float*)d_in[1];
    float* out = (float*)d_out;
    (void)in_sizes; (void)n_in; (void)out_size;

    cudaFuncSetAttribute(pair17_kernel,
                         cudaFuncAttributeMaxDynamicSharedMemorySize, DYN_SMEM);

    prep_kernel<<<PREPB, 256>>>(src, tgt);
    pair17_kernel<<<NTRI, 256, DYN_SMEM>>>(out);
}